// round 1
// baseline (speedup 1.0000x reference)
#include <cuda_runtime.h>
#include <cuda_bf16.h>

// Problem constants
#define BN 1024
#define NN 64
#define HH 512
#define MM 64
#define TB 64          // batch rows per CTA

// Shared-memory layout (float offsets)
#define SX_PITCH   68
#define SH1_PITCH  520
#define SWT_PITCH  132   // stage1/3 transposed weights: [64 k][128 h]
#define SW2T_PITCH 66    // stage2 transposed weights:   [128 k][64 m]
#define SR1_PITCH  68

#define SX_OFF   0                       // [64][68]   = 4352
#define SXN_OFF  4352                    // [64]
#define SH1_OFF  4416                    // [64][520]  = 33280
#define SW_OFF   37696                   // scratch    = 8704
#define SR1_OFF  46400                   // [64][68]   = 4352
#define SB3_OFF  50752                   // [512]
#define SW4_OFF  51264                   // [512]
#define SW3C_OFF 51776                   // [512]
#define SMEM_FLOATS 52288
#define SMEM_BYTES  (SMEM_FLOATS * 4)    // 209152 B

__global__ __launch_bounds__(256, 1)
void causal_traj_kernel(const float* __restrict__ x,
                        const float* __restrict__ W1,
                        const float* __restrict__ W2,
                        const float* __restrict__ W3,
                        const float* __restrict__ b3,
                        const float* __restrict__ W4,
                        const float* __restrict__ b4,
                        float* __restrict__ out)
{
    extern __shared__ float sm[];
    float* sX   = sm + SX_OFF;
    float* sXn  = sm + SXN_OFF;
    float* sH1  = sm + SH1_OFF;
    float* sW   = sm + SW_OFF;
    float* sR1  = sm + SR1_OFF;
    float* sB3  = sm + SB3_OFF;
    float* sW4p = sm + SW4_OFF;
    float* sW3c = sm + SW3C_OFF;

    const int n     = blockIdx.x;          // node index 0..63
    const int bbase = blockIdx.y * TB;     // batch tile start
    const int tid   = threadIdx.x;
    const int tb    = tid >> 5;            // warp id 0..7 -> b-group of 8 rows
    const int th    = tid & 31;            // lane       -> column group
    const int b0    = tb * 8;

    // ---------------- load x tile (column n zeroed) + xn ----------------
    for (int idx = tid; idx < TB * 16; idx += 256) {
        int r = idx >> 4, c4 = idx & 15;
        float4 v = *(const float4*)(x + (bbase + r) * NN + c4 * 4);
        float vv[4] = {v.x, v.y, v.z, v.w};
        int cb = c4 * 4;
        if (n >= cb && n < cb + 4) {
            sXn[r] = vv[n - cb];
            vv[n - cb] = 0.0f;
        }
        v.x = vv[0]; v.y = vv[1]; v.z = vv[2]; v.w = vv[3];
        *(float4*)(sX + r * SX_PITCH + cb) = v;
    }
    // per-node vectors for stage 3 epilogue
    for (int idx = tid; idx < HH; idx += 256) {
        sB3[idx]  = b3[n * HH + idx];
        sW4p[idx] = W4[n * HH + idx];
        sW3c[idx] = W3[n * (HH * 128) + idx * 128 + 64 + n];
    }
    __syncthreads();

    // ======================= Stage 1: H1 = relu(X1 @ W1^T) =======================
    // per node: [64 b] x [64 k] x [512 h], h in 4 chunks of 128
    const float* W1n = W1 + n * (HH * NN);
    for (int hc = 0; hc < 4; ++hc) {
        // load + transpose W1 chunk -> sW[k][r], k=0..63, r=0..127
        for (int idx = tid; idx < 128 * 16; idx += 256) {
            int r = idx >> 4, k4 = idx & 15;
            float4 v = *(const float4*)(W1n + (hc * 128 + r) * NN + k4 * 4);
            float* dst = sW + (k4 * 4) * SWT_PITCH + r;
            dst[0]             = v.x;
            dst[SWT_PITCH]     = v.y;
            dst[2 * SWT_PITCH] = v.z;
            dst[3 * SWT_PITCH] = v.w;
        }
        __syncthreads();

        float acc[8][4] = {};
        for (int k = 0; k < 64; k += 4) {
            float4 a4[8];
            #pragma unroll
            for (int i = 0; i < 8; ++i)
                a4[i] = *(const float4*)(sX + (b0 + i) * SX_PITCH + k);
            #pragma unroll
            for (int kk = 0; kk < 4; ++kk) {
                float4 w = *(const float4*)(sW + (k + kk) * SWT_PITCH + th * 4);
                #pragma unroll
                for (int i = 0; i < 8; ++i) {
                    float a = ((const float*)&a4[i])[kk];
                    acc[i][0] += a * w.x;
                    acc[i][1] += a * w.y;
                    acc[i][2] += a * w.z;
                    acc[i][3] += a * w.w;
                }
            }
        }
        __syncthreads();   // all reads of sW done before next chunk overwrites

        #pragma unroll
        for (int i = 0; i < 8; ++i) {
            float4 v;
            v.x = fmaxf(acc[i][0], 0.0f);
            v.y = fmaxf(acc[i][1], 0.0f);
            v.z = fmaxf(acc[i][2], 0.0f);
            v.w = fmaxf(acc[i][3], 0.0f);
            *(float4*)(sH1 + (b0 + i) * SH1_PITCH + hc * 128 + th * 4) = v;
        }
    }
    __syncthreads();

    // ======================= Stage 2: R1 = relu(H1 @ W2^T) =======================
    // [64 b] x [512 k] x [64 m]; thread tile 8b x 2m
    const float* W2n = W2 + n * (MM * HH);
    const int m0 = th * 2;
    float acc2[8][2] = {};
    for (int kc = 0; kc < 4; ++kc) {
        // load + transpose W2 chunk -> sW[h][m], h=0..127, m=0..63
        for (int idx = tid; idx < 64 * 32; idx += 256) {
            int m = idx >> 5, h4 = idx & 31;
            float4 v = *(const float4*)(W2n + m * HH + kc * 128 + h4 * 4);
            float* dst = sW + (h4 * 4) * SW2T_PITCH + m;
            dst[0]              = v.x;
            dst[SW2T_PITCH]     = v.y;
            dst[2 * SW2T_PITCH] = v.z;
            dst[3 * SW2T_PITCH] = v.w;
        }
        __syncthreads();

        for (int k = 0; k < 128; k += 4) {
            float4 a4[8];
            #pragma unroll
            for (int i = 0; i < 8; ++i)
                a4[i] = *(const float4*)(sH1 + (b0 + i) * SH1_PITCH + kc * 128 + k);
            #pragma unroll
            for (int kk = 0; kk < 4; ++kk) {
                float2 w = *(const float2*)(sW + (k + kk) * SW2T_PITCH + m0);
                #pragma unroll
                for (int i = 0; i < 8; ++i) {
                    float a = ((const float*)&a4[i])[kk];
                    acc2[i][0] += a * w.x;
                    acc2[i][1] += a * w.y;
                }
            }
        }
        __syncthreads();
    }
    #pragma unroll
    for (int i = 0; i < 8; ++i) {
        float2 v;
        v.x = fmaxf(acc2[i][0], 0.0f);
        v.y = fmaxf(acc2[i][1], 0.0f);
        *(float2*)(sR1 + (b0 + i) * SR1_PITCH + m0) = v;
    }
    __syncthreads();

    // ========= Stage 3: z = R1 @ W3[:, :64]^T + xn*w3col + b3; out = relu(relu(z)@W4 + b4) =========
    const float* W3n = W3 + n * (HH * 128);
    float accOut[8] = {};
    for (int hc = 0; hc < 4; ++hc) {
        // load + transpose W3 chunk (first 64 cols only) -> sW[k][r]
        for (int idx = tid; idx < 128 * 16; idx += 256) {
            int r = idx >> 4, k4 = idx & 15;
            float4 v = *(const float4*)(W3n + (hc * 128 + r) * 128 + k4 * 4);
            float* dst = sW + (k4 * 4) * SWT_PITCH + r;
            dst[0]             = v.x;
            dst[SWT_PITCH]     = v.y;
            dst[2 * SWT_PITCH] = v.z;
            dst[3 * SWT_PITCH] = v.w;
        }
        __syncthreads();

        float acc[8][4] = {};
        for (int k = 0; k < 64; k += 4) {
            float4 a4[8];
            #pragma unroll
            for (int i = 0; i < 8; ++i)
                a4[i] = *(const float4*)(sR1 + (b0 + i) * SR1_PITCH + k);
            #pragma unroll
            for (int kk = 0; kk < 4; ++kk) {
                float4 w = *(const float4*)(sW + (k + kk) * SWT_PITCH + th * 4);
                #pragma unroll
                for (int i = 0; i < 8; ++i) {
                    float a = ((const float*)&a4[i])[kk];
                    acc[i][0] += a * w.x;
                    acc[i][1] += a * w.y;
                    acc[i][2] += a * w.z;
                    acc[i][3] += a * w.w;
                }
            }
        }

        // fused epilogue: rank-1 x-term + bias, relu, dot with W4
        int hg = hc * 128 + th * 4;
        #pragma unroll
        for (int j = 0; j < 4; ++j) {
            float w3c = sW3c[hg + j];
            float bb  = sB3[hg + j];
            float w4v = sW4p[hg + j];
            #pragma unroll
            for (int i = 0; i < 8; ++i) {
                float z = acc[i][j] + sXn[b0 + i] * w3c + bb;
                accOut[i] += fmaxf(z, 0.0f) * w4v;
            }
        }
        __syncthreads();   // sW reads done before next chunk's transpose writes
    }

    // warp-level reduction over the 32 h-lanes
    #pragma unroll
    for (int i = 0; i < 8; ++i) {
        float v = accOut[i];
        #pragma unroll
        for (int o = 16; o > 0; o >>= 1)
            v += __shfl_xor_sync(0xffffffffu, v, o);
        accOut[i] = v;
    }
    if (th == 0) {
        float bb4 = b4[n];
        #pragma unroll
        for (int i = 0; i < 8; ++i)
            out[(bbase + b0 + i) * NN + n] = fmaxf(accOut[i] + bb4, 0.0f);
    }
}

extern "C" void kernel_launch(void* const* d_in, const int* in_sizes, int n_in,
                              void* d_out, int out_size)
{
    const float* x  = (const float*)d_in[0];
    const float* W1 = (const float*)d_in[1];
    const float* W2 = (const float*)d_in[2];
    const float* W3 = (const float*)d_in[3];
    const float* b3 = (const float*)d_in[4];
    const float* W4 = (const float*)d_in[5];
    const float* b4 = (const float*)d_in[6];
    float* out = (float*)d_out;

    cudaFuncSetAttribute(causal_traj_kernel,
                         cudaFuncAttributeMaxDynamicSharedMemorySize, SMEM_BYTES);

    dim3 grid(NN, BN / TB);   // (64 nodes, 16 batch tiles)
    causal_traj_kernel<<<grid, 256, SMEM_BYTES>>>(x, W1, W2, W3, b3, W4, b4, out);
}

// round 3
// speedup vs baseline: 3.1088x; 3.1088x over previous
#include <cuda_runtime.h>
#include <cuda_fp16.h>
#include <cstdint>

#define NN 64
#define HH 512
#define TB 128

#define PIT1 136   // pitch in halves for K=64 hi|lo tiles (X/A3, W1/W3 chunks)
#define PIT2 264   // pitch in halves for K=128 hi|lo tiles (A2, W2 chunk)

// shared memory byte offsets
#define OFF_XN    0          // 128 floats
#define OFF_EPI   512        // 512 * float4 = 8192
#define OFF_X     8704       // 128*136*2 = 34816   (X hi|lo; later A3)
#define OFF_W13   43520      // 128*136*2 = 34816   (W1 / W3 chunk)
#define OFF_W2    78336      // 64*264*2  = 33792   (W2 chunk; later reduce buf)
#define OFF_A2    112128     // 128*264*2 = 67584   (relu(H1) chunk)
#define SMEM_BYTES 179712

// ---------------------------------------------------------------- helpers
__device__ __forceinline__ void mma16816(float c[4],
                                         uint32_t a0, uint32_t a1, uint32_t a2, uint32_t a3,
                                         uint32_t b0, uint32_t b1) {
    asm volatile(
        "mma.sync.aligned.m16n8k16.row.col.f32.f16.f16.f32 "
        "{%0,%1,%2,%3}, {%4,%5,%6,%7}, {%8,%9}, {%0,%1,%2,%3};\n"
        : "+f"(c[0]), "+f"(c[1]), "+f"(c[2]), "+f"(c[3])
        : "r"(a0), "r"(a1), "r"(a2), "r"(a3), "r"(b0), "r"(b1));
}

// split a,b into fp16 hi/lo and store as half2 pairs
__device__ __forceinline__ void split_store2(__half* hiP, __half* loP, float a, float b) {
    __half ha = __float2half_rn(a), hb = __float2half_rn(b);
    __half la = __float2half_rn(a - __half2float(ha));
    __half lb = __float2half_rn(b - __half2float(hb));
    *(__half2*)hiP = __halves2half2(ha, hb);
    *(__half2*)loP = __halves2half2(la, lb);
}
// split 4 consecutive floats; hi at [0..3], lo at loP[0..3]
__device__ __forceinline__ void split_store4(__half* hiP, __half* loP, float4 v) {
    split_store2(hiP,     loP,     v.x, v.y);
    split_store2(hiP + 2, loP + 2, v.z, v.w);
}

// K=64 hi|lo GEMM: C[warp 32b x 64n] += A[128b][hi|lo] * W[128n][hi|lo]^T
// 3 compensation passes: hi*hi, lo*hi, hi*lo
__device__ __forceinline__ void gemm64(const __half* At, const __half* Wt,
                                       int bq, int hh, int g, int tg,
                                       float acc[2][8][4]) {
    const int pa[3] = {0, 64, 0};
    const int pb[3] = {0, 0, 64};
    #pragma unroll
    for (int p = 0; p < 3; ++p) {
        #pragma unroll
        for (int ks = 0; ks < 4; ++ks) {
            const int kA = pa[p] + ks * 16 + tg * 2;
            const int kB = pb[p] + ks * 16 + tg * 2;
            uint32_t a[2][4];
            #pragma unroll
            for (int mt = 0; mt < 2; ++mt) {
                const __half* base = At + (bq * 32 + mt * 16 + g) * PIT1 + kA;
                a[mt][0] = *(const uint32_t*)(base);
                a[mt][1] = *(const uint32_t*)(base + 8 * PIT1);
                a[mt][2] = *(const uint32_t*)(base + 8);
                a[mt][3] = *(const uint32_t*)(base + 8 * PIT1 + 8);
            }
            #pragma unroll
            for (int j = 0; j < 8; ++j) {
                const __half* bb = Wt + (hh * 64 + j * 8 + g) * PIT1 + kB;
                uint32_t b0 = *(const uint32_t*)(bb);
                uint32_t b1 = *(const uint32_t*)(bb + 8);
                mma16816(acc[0][j], a[0][0], a[0][1], a[0][2], a[0][3], b0, b1);
                mma16816(acc[1][j], a[1][0], a[1][1], a[1][2], a[1][3], b0, b1);
            }
        }
    }
}

// ---------------------------------------------------------------- kernel
__global__ __launch_bounds__(256, 1)
void ctp_hmma_kernel(const float* __restrict__ x,
                     const float* __restrict__ W1,
                     const float* __restrict__ W2,
                     const float* __restrict__ W3,
                     const float* __restrict__ b3,
                     const float* __restrict__ W4,
                     const float* __restrict__ b4,
                     float* __restrict__ out)
{
    extern __shared__ char sm[];
    float*  sXn  = (float*)(sm + OFF_XN);
    float4* sEpi = (float4*)(sm + OFF_EPI);
    __half* Xt   = (__half*)(sm + OFF_X);
    __half* W13t = (__half*)(sm + OFF_W13);
    __half* W2t  = (__half*)(sm + OFF_W2);
    __half* A2t  = (__half*)(sm + OFF_A2);

    const int tid  = threadIdx.x;
    const int wid  = tid >> 5;
    const int lane = tid & 31;
    const int g    = lane >> 2;    // group id (row within 8)
    const int tg   = lane & 3;     // thread-in-group (col pair)
    const int bq   = wid & 3;      // warp's 32-row batch group
    const int hh   = wid >> 2;     // warp's column half
    const int n    = blockIdx.x;
    const int r0   = blockIdx.y * TB;

    // ---- prologue: X tile (col n zeroed, xn captured) + epilogue vectors ----
    {
        const int row = tid >> 1, hf = tid & 1;
        const float* xr = x + (r0 + row) * NN + hf * 32;
        #pragma unroll
        for (int i = 0; i < 8; ++i) {
            const int c = hf * 32 + i * 4;
            float4 v = *(const float4*)(xr + i * 4);
            if (n >= c && n < c + 4) {
                float vv[4] = {v.x, v.y, v.z, v.w};
                sXn[row] = vv[n - c];
                vv[n - c] = 0.0f;
                v = make_float4(vv[0], vv[1], vv[2], vv[3]);
            }
            split_store4(Xt + row * PIT1 + c, Xt + row * PIT1 + 64 + c, v);
        }
    }
    for (int idx = tid; idx < HH; idx += 256)
        sEpi[idx] = make_float4(W3[(n * HH + idx) * 128 + 64 + n],
                                b3[n * HH + idx],
                                W4[n * HH + idx], 0.0f);
    const float b4n = b4[n];

    float acc2[2][4][4] = {};   // D2 [128b x 64m], persistent across chunks

    // =================== Stages 1+2 over 4 H-chunks of 128 ===================
    for (int hc = 0; hc < 4; ++hc) {
        __syncthreads();   // prev chunk consumers done before overwriting tiles
        // load + split W1 chunk [128h x 64k]
        for (int idx = tid; idx < 2048; idx += 256) {
            const int row = idx >> 4, q = (idx & 15) * 4;
            float4 v = *(const float4*)(W1 + n * (HH * NN) + (hc * 128 + row) * NN + q);
            split_store4(W13t + row * PIT1 + q, W13t + row * PIT1 + 64 + q, v);
        }
        // load + split W2 chunk [64m x 128k]
        for (int idx = tid; idx < 2048; idx += 256) {
            const int m = idx >> 5, q = (idx & 31) * 4;
            float4 v = *(const float4*)(W2 + n * (NN * HH) + m * HH + hc * 128 + q);
            split_store4(W2t + m * PIT2 + q, W2t + m * PIT2 + 128 + q, v);
        }
        __syncthreads();

        // ---- stage 1: D1 chunk [128b x 128h] = X @ W1c^T ----
        float acc1[2][8][4] = {};
        gemm64(Xt, W13t, bq, hh, g, tg, acc1);

        // relu + split-store into A2 (each thread writes its own C values)
        #pragma unroll
        for (int mt = 0; mt < 2; ++mt) {
            const int r = bq * 32 + mt * 16 + g;
            #pragma unroll
            for (int j = 0; j < 8; ++j) {
                const int c = hh * 64 + j * 8 + tg * 2;
                split_store2(A2t + r * PIT2 + c,        A2t + r * PIT2 + 128 + c,
                             fmaxf(acc1[mt][j][0], 0.f), fmaxf(acc1[mt][j][1], 0.f));
                split_store2(A2t + (r + 8) * PIT2 + c,  A2t + (r + 8) * PIT2 + 128 + c,
                             fmaxf(acc1[mt][j][2], 0.f), fmaxf(acc1[mt][j][3], 0.f));
            }
        }
        __syncthreads();

        // ---- stage 2 partial: D2 += A2chunk @ W2chunk^T  (K=128, 3 passes) ----
        {
            const int pa[3] = {0, 128, 0};
            const int pb[3] = {0, 0, 128};
            #pragma unroll
            for (int p = 0; p < 3; ++p) {
                #pragma unroll
                for (int ks = 0; ks < 8; ++ks) {
                    const int kA = pa[p] + ks * 16 + tg * 2;
                    const int kB = pb[p] + ks * 16 + tg * 2;
                    uint32_t a[2][4];
                    #pragma unroll
                    for (int mt = 0; mt < 2; ++mt) {
                        const __half* base = A2t + (bq * 32 + mt * 16 + g) * PIT2 + kA;
                        a[mt][0] = *(const uint32_t*)(base);
                        a[mt][1] = *(const uint32_t*)(base + 8 * PIT2);
                        a[mt][2] = *(const uint32_t*)(base + 8);
                        a[mt][3] = *(const uint32_t*)(base + 8 * PIT2 + 8);
                    }
                    #pragma unroll
                    for (int j = 0; j < 4; ++j) {
                        const __half* bb = W2t + (hh * 32 + j * 8 + g) * PIT2 + kB;
                        uint32_t b0 = *(const uint32_t*)(bb);
                        uint32_t b1 = *(const uint32_t*)(bb + 8);
                        mma16816(acc2[0][j], a[0][0], a[0][1], a[0][2], a[0][3], b0, b1);
                        mma16816(acc2[1][j], a[1][0], a[1][1], a[1][2], a[1][3], b0, b1);
                    }
                }
            }
        }
    }

    // ---- A3 = relu(D2) -> hi/lo into X buffer (X dead after stage 1) ----
    __syncthreads();
    #pragma unroll
    for (int mt = 0; mt < 2; ++mt) {
        const int r = bq * 32 + mt * 16 + g;
        #pragma unroll
        for (int j = 0; j < 4; ++j) {
            const int c = hh * 32 + j * 8 + tg * 2;
            split_store2(Xt + r * PIT1 + c,       Xt + r * PIT1 + 64 + c,
                         fmaxf(acc2[mt][j][0], 0.f), fmaxf(acc2[mt][j][1], 0.f));
            split_store2(Xt + (r + 8) * PIT1 + c, Xt + (r + 8) * PIT1 + 64 + c,
                         fmaxf(acc2[mt][j][2], 0.f), fmaxf(acc2[mt][j][3], 0.f));
        }
    }

    // per-thread xn for its 4 rows
    float xnv[4];
    #pragma unroll
    for (int i = 0; i < 4; ++i) xnv[i] = sXn[bq * 32 + i * 8 + g];

    // =================== Stage 3 over 4 H-chunks, fused epilogue ===================
    float rowSum[4] = {};
    for (int hc = 0; hc < 4; ++hc) {
        __syncthreads();   // prior consumers of W13 done
        for (int idx = tid; idx < 2048; idx += 256) {
            const int row = idx >> 4, q = (idx & 15) * 4;
            float4 v = *(const float4*)(W3 + n * (HH * 128) + (hc * 128 + row) * 128 + q);
            split_store4(W13t + row * PIT1 + q, W13t + row * PIT1 + 64 + q, v);
        }
        __syncthreads();

        float acc3[2][8][4] = {};
        gemm64(Xt, W13t, bq, hh, g, tg, acc3);

        // epilogue: z = d3 + xn*w3col + b3 ; rowSum += relu(z)*w4
        #pragma unroll
        for (int j = 0; j < 8; ++j) {
            const int colb = hc * 128 + hh * 64 + j * 8 + tg * 2;
            const float4 e0 = sEpi[colb];
            const float4 e1 = sEpi[colb + 1];
            #pragma unroll
            for (int mt = 0; mt < 2; ++mt) {
                float z;
                z = acc3[mt][j][0] + xnv[mt * 2]     * e0.x + e0.y;
                rowSum[mt * 2]     += fmaxf(z, 0.f) * e0.z;
                z = acc3[mt][j][1] + xnv[mt * 2]     * e1.x + e1.y;
                rowSum[mt * 2]     += fmaxf(z, 0.f) * e1.z;
                z = acc3[mt][j][2] + xnv[mt * 2 + 1] * e0.x + e0.y;
                rowSum[mt * 2 + 1] += fmaxf(z, 0.f) * e0.z;
                z = acc3[mt][j][3] + xnv[mt * 2 + 1] * e1.x + e1.y;
                rowSum[mt * 2 + 1] += fmaxf(z, 0.f) * e1.z;
            }
        }
    }
    __syncthreads();   // all W13 reads done; W2 region free for reduction

    // reduce across the 4 threads of each group, then across the two column-half warps
    float* Pred = (float*)(sm + OFF_W2);   // [2][128]
    #pragma unroll
    for (int i = 0; i < 4; ++i) {
        float v = rowSum[i];
        v += __shfl_xor_sync(0xffffffffu, v, 1);
        v += __shfl_xor_sync(0xffffffffu, v, 2);
        if (tg == 0) Pred[hh * 128 + bq * 32 + i * 8 + g] = v;
    }
    __syncthreads();
    if (tid < 128) {
        const float tot = Pred[tid] + Pred[128 + tid];
        out[(r0 + tid) * NN + n] = fmaxf(tot + b4n, 0.0f);
    }
}

extern "C" void kernel_launch(void* const* d_in, const int* in_sizes, int n_in,
                              void* d_out, int out_size)
{
    const float* x  = (const float*)d_in[0];
    const float* W1 = (const float*)d_in[1];
    const float* W2 = (const float*)d_in[2];
    const float* W3 = (const float*)d_in[3];
    const float* b3 = (const float*)d_in[4];
    const float* W4 = (const float*)d_in[5];
    const float* b4 = (const float*)d_in[6];
    float* out = (float*)d_out;

    cudaFuncSetAttribute(ctp_hmma_kernel,
                         cudaFuncAttributeMaxDynamicSharedMemorySize, SMEM_BYTES);

    dim3 grid(NN, 1024 / TB);   // (64 nodes, 8 batch tiles of 128)
    ctp_hmma_kernel<<<grid, 256, SMEM_BYTES>>>(x, W1, W2, W3, b3, W4, b4, out);
}